// round 16
// baseline (speedup 1.0000x reference)
#include <cuda_runtime.h>
#include <cuda_bf16.h>
#include <math.h>
#include <stdint.h>

#define Bv 256
#define Nv 128
#define Dv 512
#define BNv (Bv*Nv)

// ---------------- device scratch ----------------
__device__ float         g_H [(size_t)BNv*Dv];
__device__ float         g_H2[(size_t)BNv*Dv];
__device__ __nv_bfloat16 g_Ebf[(size_t)BNv*Dv];
__device__ __nv_bfloat16 g_Ubf[(size_t)BNv*Dv];
__device__ __nv_bfloat16 g_WTbf[3*Dv*Dv];
__device__ float g_mask[BNv];
__device__ float g_cnt[Bv];
__device__ float g_part_t[BNv];
__device__ float g_part_s[BNv];
__device__ float g_part_c[Bv];
__device__ int   g_mfmt;

// ---------------- helpers ----------------
__device__ __forceinline__ uint32_t s2u(const void* p){
    uint32_t a;
    asm("{ .reg .u64 t; cvta.to.shared.u64 t, %1; cvt.u32.u64 %0, t; }":"=r"(a):"l"(p));
    return a;
}
__device__ __forceinline__ float htanh(float x){
    float t; asm("tanh.approx.f32 %0, %1;":"=f"(t):"f"(x));
    return t;
}
__device__ __forceinline__ float gelu_fast(float x){
    float x2 = x*x;
    float inner = x*fmaf(0.044715f*0.7978845608f, x2, 0.7978845608f);
    return 0.5f*x*(1.f + htanh(inner));
}
__device__ __forceinline__ void mma_bf16(float* d, const uint32_t* a, uint32_t b0, uint32_t b1){
    asm volatile(
      "mma.sync.aligned.m16n8k16.row.col.f32.bf16.bf16.f32 "
      "{%0,%1,%2,%3}, {%4,%5,%6,%7}, {%8,%9}, {%0,%1,%2,%3};"
      : "+f"(d[0]),"+f"(d[1]),"+f"(d[2]),"+f"(d[3])
      : "r"(a[0]),"r"(a[1]),"r"(a[2]),"r"(a[3]), "r"(b0),"r"(b1));
}
__device__ __forceinline__ void ldsm4(uint32_t addr, uint32_t* r){
    asm volatile("ldmatrix.sync.aligned.m8n8.x4.shared.b16 {%0,%1,%2,%3}, [%4];"
        : "=r"(r[0]),"=r"(r[1]),"=r"(r[2]),"=r"(r[3]) : "r"(addr));
}
__device__ __forceinline__ float warpAllSum(float v){
    #pragma unroll
    for(int o=16;o>0;o>>=1) v += __shfl_xor_sync(0xffffffffu, v, o);
    return v;
}
__device__ __forceinline__ uint32_t packbf(float a, float b){
    __nv_bfloat162 p = __floats2bfloat162_rn(a,b);
    return *reinterpret_cast<uint32_t*>(&p);
}

// ---------------- mask format detection + merged mask/count ----------------
__global__ void k_detect(const unsigned int* __restrict__ raw){
    __shared__ int f[2];
    if(threadIdx.x==0){ f[0]=1; f[1]=1; }
    __syncthreads();
    for(int i=threadIdx.x;i<8192;i+=256){
        unsigned v = raw[i];
        if(v>1u) f[0]=0;
        if(v!=0u && v!=0x3F800000u) f[1]=0;
    }
    __syncthreads();
    if(threadIdx.x==0) g_mfmt = f[0] ? 0 : (f[1] ? 1 : 2);
}
__global__ void k_maskcnt(const void* __restrict__ raw){
    int b = blockIdx.x, tid = threadIdx.x;
    int i = b*Nv + tid;
    int fmt = g_mfmt;
    float m;
    if(fmt==0)      m = (((const int*)raw)[i]   != 0)    ? 1.f : 0.f;
    else if(fmt==1) m = (((const float*)raw)[i] != 0.f)  ? 1.f : 0.f;
    else            m = (((const unsigned char*)raw)[i]!=0) ? 1.f : 0.f;
    g_mask[i] = m;
    float v = m;
    #pragma unroll
    for(int o=16;o>0;o>>=1) v += __shfl_down_sync(0xffffffffu, v, o);
    __shared__ float sh[4];
    if((tid&31)==0) sh[tid>>5] = v;
    __syncthreads();
    if(tid==0) g_cnt[b] = sh[0]+sh[1]+sh[2]+sh[3];
}

// ---------------- convert e -> bf16 ----------------
__global__ void k_cvt(const float* __restrict__ e){
    size_t i = (size_t)blockIdx.x*256 + threadIdx.x;
    float4 v = reinterpret_cast<const float4*>(e)[i];
    uint2 o;
    o.x = packbf(v.x, v.y);
    o.y = packbf(v.z, v.w);
    reinterpret_cast<uint2*>(g_Ebf)[i] = o;
}

// ---------------- weight transpose -> bf16 ----------------
__global__ void k_transpose3(const float* __restrict__ W0, const float* __restrict__ W1,
                             const float* __restrict__ W2){
    __shared__ float t[32][33];
    const float* W = (blockIdx.z==0) ? W0 : (blockIdx.z==1 ? W1 : W2);
    __nv_bfloat16* dst = g_WTbf + (size_t)blockIdx.z*Dv*Dv;
    int bx = blockIdx.x*32, by = blockIdx.y*32;
    int x = threadIdx.x, y = threadIdx.y;
    #pragma unroll
    for(int i=0;i<32;i+=8) t[y+i][x] = W[(size_t)(by+y+i)*Dv + bx+x];
    __syncthreads();
    #pragma unroll
    for(int i=0;i<32;i+=8) dst[(size_t)(bx+y+i)*Dv + by+x] = __float2bfloat16(t[x][y+i]);
}

// ---------------- bf16 mma GEMM core: 128 threads, 4 warps of 64x64 tiles ----------------
#define NCHB   8
#define STH    72
#define TILE_H (128*STH)
#define BUFB   36864
#define SMEM_SZ (2*BUFB)

// OUT 1 = GELU->g_H ; 2 = GELU->g_H2 ; 3 = U->g_Ubf ; 4 = corr epilogue
template<int OUT>
__device__ __forceinline__ void gemm_body(
    const __nv_bfloat16* __restrict__ Ab, const __nv_bfloat16* __restrict__ Bb,
    float* sm, uint32_t sb, int m0, int n0,
    const float* __restrict__ bias,
    const float* __restrict__ corr_t, const float* __restrict__ cb_ptr, int b){

    int tid = threadIdx.x, lane = tid&31, wid = tid>>5;  // 4 warps
    int g = lane>>2, t = lane&3;
    int wm = (wid&1)*64, wn = (wid>>1)*64;   // 2x2 warp grid, 64x64 per warp

    int lrow = lane&15, lhi = lane>>4;
    uint32_t aoff[4], boff[4];
    #pragma unroll
    for(int mi=0;mi<4;mi++)
        aoff[mi] = (uint32_t)(((wm+mi*16+lrow)*36 + lhi*4)*4);
    #pragma unroll
    for(int p=0;p<4;p++)
        boff[p]  = (uint32_t)(TILE_H*2 + ((wn+p*16+lrow)*36 + lhi*4)*4);

    float acc[4][8][4];
    #pragma unroll
    for(int mi=0;mi<4;mi++)
        #pragma unroll
        for(int nj=0;nj<8;nj++)
            #pragma unroll
            for(int q=0;q<4;q++) acc[mi][nj][q]=0.f;

    auto stage = [&](int c, int buf){
        #pragma unroll
        for(int i=0;i<8;i++){
            int fi = tid + i*128;
            int row = fi>>3, q = fi&7;
            const __nv_bfloat16* ga = Ab + (size_t)row*Dv + c*64 + q*8;
            const __nv_bfloat16* gb = Bb + (size_t)row*Dv + c*64 + q*8;
            uint32_t da = sb + (uint32_t)(buf*BUFB + row*144 + q*16);
            uint32_t db = da + (uint32_t)(TILE_H*2);
            asm volatile("cp.async.ca.shared.global [%0], [%1], 16;"::"r"(da),"l"(ga):"memory");
            asm volatile("cp.async.ca.shared.global [%0], [%1], 16;"::"r"(db),"l"(gb):"memory");
        }
        asm volatile("cp.async.commit_group;":::"memory");
    };

    stage(0,0);

    #pragma unroll 1
    for(int c=0;c<NCHB;c++){
        if(c+1<NCHB){
            stage(c+1,(c+1)&1);
            asm volatile("cp.async.wait_group 1;":::"memory");
        }else{
            asm volatile("cp.async.wait_group 0;":::"memory");
        }
        __syncthreads();
        uint32_t base = sb + (uint32_t)((c&1)*BUFB);
        #pragma unroll
        for(int ki=0;ki<4;ki++){
            uint32_t af[4][4], bf[4][4];
            #pragma unroll
            for(int mi=0;mi<4;mi++) ldsm4(base + aoff[mi] + ki*32, af[mi]);
            #pragma unroll
            for(int p=0;p<4;p++)    ldsm4(base + boff[p]  + ki*32, bf[p]);
            #pragma unroll
            for(int p=0;p<4;p++){
                #pragma unroll
                for(int mi=0;mi<4;mi++){
                    mma_bf16(acc[mi][2*p],   af[mi], bf[p][0], bf[p][2]);
                    mma_bf16(acc[mi][2*p+1], af[mi], bf[p][1], bf[p][3]);
                }
            }
        }
        __syncthreads();
    }

    if(OUT==1 || OUT==2){
        float* Hout = (OUT==1) ? g_H : g_H2;
        #pragma unroll
        for(int mi=0;mi<4;mi++){
            int r0 = m0 + wm + mi*16 + g;
            #pragma unroll
            for(int nj=0;nj<8;nj++){
                int cc = n0 + wn + nj*8 + 2*t;
                float bb0 = bias[cc], bb1 = bias[cc+1];
                float x0=gelu_fast(acc[mi][nj][0]+bb0), x1=gelu_fast(acc[mi][nj][1]+bb1);
                float x2=gelu_fast(acc[mi][nj][2]+bb0), x3=gelu_fast(acc[mi][nj][3]+bb1);
                *reinterpret_cast<float2*>(&Hout[(size_t)r0*Dv + cc])     = make_float2(x0,x1);
                *reinterpret_cast<float2*>(&Hout[(size_t)(r0+8)*Dv + cc]) = make_float2(x2,x3);
            }
        }
    }else if(OUT==3){
        #pragma unroll
        for(int mi=0;mi<4;mi++){
            int r0 = m0 + wm + mi*16 + g;
            #pragma unroll
            for(int nj=0;nj<8;nj++){
                int cc = n0 + wn + nj*8 + 2*t;
                *reinterpret_cast<uint32_t*>(&g_Ubf[(size_t)r0*Dv + cc])
                    = packbf(acc[mi][nj][0], acc[mi][nj][1]);
                *reinterpret_cast<uint32_t*>(&g_Ubf[(size_t)(r0+8)*Dv + cc])
                    = packbf(acc[mi][nj][2], acc[mi][nj][3]);
            }
        }
    }else{
        float cb = *cb_ptr;
        const float* msk = g_mask + b*Nv;
        const float* ct  = corr_t + (size_t)b*Nv*Nv;
        float local = 0.f;
        #pragma unroll
        for(int mi=0;mi<4;mi++){
            int r0 = wm + mi*16 + g;
            float mr0 = msk[r0], mr8 = msk[r0+8];
            #pragma unroll
            for(int nj=0;nj<8;nj++){
                int cc = wn + nj*8 + 2*t;
                float mc0 = msk[cc], mc1 = msk[cc+1];
                float2 t0 = *reinterpret_cast<const float2*>(&ct[(size_t)r0*Nv + cc]);
                float2 t1 = *reinterpret_cast<const float2*>(&ct[(size_t)(r0+8)*Nv + cc]);
                float s0 = (r0==cc)     ? 1.f : htanh(acc[mi][nj][0]+cb);
                float s1 = (r0==cc+1)   ? 1.f : htanh(acc[mi][nj][1]+cb);
                float s2 = (r0+8==cc)   ? 1.f : htanh(acc[mi][nj][2]+cb);
                float s3 = (r0+8==cc+1) ? 1.f : htanh(acc[mi][nj][3]+cb);
                float d0=s0-t0.x, d1=s1-t0.y, d2=s2-t1.x, d3=s3-t1.y;
                local += fmaxf(mr0,mc0)*d0*d0 + fmaxf(mr0,mc1)*d1*d1
                       + fmaxf(mr8,mc0)*d2*d2 + fmaxf(mr8,mc1)*d3*d3;
            }
        }
        #pragma unroll
        for(int o=16;o>0;o>>=1) local += __shfl_down_sync(0xffffffffu, local, o);
        if(lane==0) sm[wid] = local;
        __syncthreads();
        if(tid==0){
            float tot = sm[0]+sm[1]+sm[2]+sm[3];
            g_part_c[b] = tot;
        }
    }
}

// per-slot GEMMs: grid (4, 256), 128 threads, 3 CTAs/SM
__global__ void __launch_bounds__(128,3)
k_gemm_t(const float* __restrict__ tb1){
    extern __shared__ float sm[];
    uint32_t sb = s2u(sm);
    int n0 = blockIdx.x*128, m0 = blockIdx.y*128;
    gemm_body<1>(g_Ebf + (size_t)m0*Dv, g_WTbf + (size_t)n0*Dv,
                 sm, sb, m0, n0, tb1, nullptr, nullptr, 0);
}
__global__ void __launch_bounds__(128,3)
k_gemm_s(const float* __restrict__ sb1){
    extern __shared__ float sm[];
    uint32_t sb = s2u(sm);
    int n0 = blockIdx.x*128, m0 = blockIdx.y*128;
    gemm_body<2>(g_Ebf + (size_t)m0*Dv, g_WTbf + (size_t)1*Dv*Dv + (size_t)n0*Dv,
                 sm, sb, m0, n0, sb1, nullptr, nullptr, 0);
}
__global__ void __launch_bounds__(128,3)
k_gemm_u(){
    extern __shared__ float sm[];
    uint32_t sb = s2u(sm);
    int n0 = blockIdx.x*128, m0 = blockIdx.y*128;
    gemm_body<3>(g_Ebf + (size_t)m0*Dv, g_WTbf + (size_t)2*Dv*Dv + (size_t)n0*Dv,
                 sm, sb, m0, n0, nullptr, nullptr, nullptr, 0);
}
__global__ void __launch_bounds__(128,3)
k_corr_bf(const float* __restrict__ corr_t, const float* __restrict__ cb_ptr){
    extern __shared__ float sm[];
    uint32_t sb = s2u(sm);
    int b = blockIdx.x;
    const __nv_bfloat16* Ab = g_Ubf + (size_t)b*Nv*Dv;
    const __nv_bfloat16* Bb = g_Ebf + (size_t)b*Nv*Dv;
    gemm_body<4>(Ab, Bb, sm, sb, 0, 0, nullptr, corr_t, cb_ptr, b);
}

// ---------------- warp-per-row heads ----------------
__global__ void __launch_bounds__(256) k_type(const float* __restrict__ W2,
                                              const float* __restrict__ b2,
                                              const float* __restrict__ gam,
                                              const float* __restrict__ bet,
                                              const int* __restrict__ tgt){
    int wid = threadIdx.x>>5, lane = threadIdx.x&31;
    int row = blockIdx.x*8 + wid;
    const float4* h4 = reinterpret_cast<const float4*>(g_H + (size_t)row*Dv);
    float4 x[4];
    #pragma unroll
    for(int i=0;i<4;i++) x[i] = h4[lane + 32*i];
    float s = 0.f;
    #pragma unroll
    for(int i=0;i<4;i++) s += x[i].x+x[i].y+x[i].z+x[i].w;
    float mu = warpAllSum(s) * (1.f/Dv);
    float vv = 0.f;
    #pragma unroll
    for(int i=0;i<4;i++){
        float a=x[i].x-mu,b=x[i].y-mu,c=x[i].z-mu,d=x[i].w-mu;
        vv += a*a+b*b+c*c+d*d;
    }
    float rs = rsqrtf(warpAllSum(vv)*(1.f/Dv) + 1e-5f);
    float p[6] = {0,0,0,0,0,0};
    #pragma unroll
    for(int i=0;i<4;i++){
        int r0 = lane*4 + 128*i;
        float4 g4 = reinterpret_cast<const float4*>(gam)[lane+32*i];
        float4 b4 = reinterpret_cast<const float4*>(bet)[lane+32*i];
        float y[4];
        y[0]=(x[i].x-mu)*rs*g4.x+b4.x; y[1]=(x[i].y-mu)*rs*g4.y+b4.y;
        y[2]=(x[i].z-mu)*rs*g4.z+b4.z; y[3]=(x[i].w-mu)*rs*g4.w+b4.w;
        float wf[24];
        const float4* w4 = reinterpret_cast<const float4*>(W2 + (size_t)r0*6);
        #pragma unroll
        for(int j=0;j<6;j++) reinterpret_cast<float4*>(wf)[j] = w4[j];
        #pragma unroll
        for(int r=0;r<4;r++)
            #pragma unroll
            for(int c=0;c<6;c++) p[c] = fmaf(y[r], wf[r*6+c], p[c]);
    }
    #pragma unroll
    for(int c=0;c<6;c++) p[c] = warpAllSum(p[c]);
    if(lane==0){
        float mx = -1e30f;
        #pragma unroll
        for(int c=0;c<6;c++){ p[c] += b2[c]; mx = fmaxf(mx, p[c]); }
        float se = 0.f;
        #pragma unroll
        for(int c=0;c<6;c++) se += expf(p[c]-mx);
        float lse = mx + logf(se);
        int tt = tgt[row & (Nv-1)];
        g_part_t[row] = g_mask[row] * (lse - p[tt]);
    }
}

__global__ void __launch_bounds__(256) k_stats(const float* __restrict__ W2,
                                               const float* __restrict__ b2,
                                               const float* __restrict__ gam,
                                               const float* __restrict__ bet,
                                               const float* __restrict__ st){
    int wid = threadIdx.x>>5, lane = threadIdx.x&31;
    int row = blockIdx.x*8 + wid;
    const float4* h4 = reinterpret_cast<const float4*>(g_H2 + (size_t)row*Dv);
    float4 x[4];
    #pragma unroll
    for(int i=0;i<4;i++) x[i] = h4[lane + 32*i];
    float s = 0.f;
    #pragma unroll
    for(int i=0;i<4;i++) s += x[i].x+x[i].y+x[i].z+x[i].w;
    float mu = warpAllSum(s) * (1.f/Dv);
    float vv = 0.f;
    #pragma unroll
    for(int i=0;i<4;i++){
        float a=x[i].x-mu,b=x[i].y-mu,c=x[i].z-mu,d=x[i].w-mu;
        vv += a*a+b*b+c*c+d*d;
    }
    float rs = rsqrtf(warpAllSum(vv)*(1.f/Dv) + 1e-5f);
    float p[8] = {0,0,0,0,0,0,0,0};
    #pragma unroll
    for(int i=0;i<4;i++){
        int r0 = lane*4 + 128*i;
        float4 g4 = reinterpret_cast<const float4*>(gam)[lane+32*i];
        float4 b4 = reinterpret_cast<const float4*>(bet)[lane+32*i];
        float y[4];
        y[0]=(x[i].x-mu)*rs*g4.x+b4.x; y[1]=(x[i].y-mu)*rs*g4.y+b4.y;
        y[2]=(x[i].z-mu)*rs*g4.z+b4.z; y[3]=(x[i].w-mu)*rs*g4.w+b4.w;
        float wf[32];
        const float4* w4 = reinterpret_cast<const float4*>(W2 + (size_t)r0*8);
        #pragma unroll
        for(int j=0;j<8;j++) reinterpret_cast<float4*>(wf)[j] = w4[j];
        #pragma unroll
        for(int r=0;r<4;r++)
            #pragma unroll
            for(int c=0;c<8;c++) p[c] = fmaf(y[r], wf[r*8+c], p[c]);
    }
    #pragma unroll
    for(int c=0;c<8;c++) p[c] = warpAllSum(p[c]);
    if(lane==0){
        float ssum = 0.f;
        #pragma unroll
        for(int c=0;c<8;c++){
            float d = p[c] + b2[c] - st[(size_t)row*8 + c];
            ssum += d*d;
        }
        g_part_s[row] = g_mask[row] * ssum;
    }
}

// ---------------- final deterministic combine ----------------
__global__ void k_final(float* __restrict__ out){
    __shared__ double sh[1024];
    int tid = threadIdx.x;
    double tsum=0, ssum=0, csum=0, nm=0, nme=0;
    for(int i=tid;i<BNv;i+=1024){ tsum += (double)g_part_t[i]; ssum += (double)g_part_s[i]; }
    for(int i=tid;i<Bv;i+=1024){
        csum += (double)g_part_c[i];
        double cnt = (double)g_cnt[i];
        nm += cnt;
        double u = (double)Nv - cnt;
        nme += (double)Nv*(double)Nv - u*u;
    }
    double vals[5] = {tsum, ssum, csum, nm, nme};
    for(int v=0;v<5;v++){
        sh[tid] = vals[v]; __syncthreads();
        for(int o=512;o>0;o>>=1){ if(tid<o) sh[tid]+=sh[tid+o]; __syncthreads(); }
        vals[v] = sh[0]; __syncthreads();
    }
    if(tid==0){
        double nm_  = vals[3] < 1.0 ? 1.0 : vals[3];
        double nme_ = vals[4] < 1.0 ? 1.0 : vals[4];
        double total = vals[0]/nm_ + vals[1]/(nm_*8.0) + 0.5*vals[2]/nme_;
        out[0] = (float)total;
    }
}

// ---------------- launch (forked-stream graph, U-first ordering) ----------------
extern "C" void kernel_launch(void* const* d_in, const int* in_sizes, int n_in,
                              void* d_out, int out_size){
    const float* e     = (const float*)d_in[0];
    const void*  mraw  = d_in[1];
    const int*   tgt   = (const int*)d_in[2];
    const float* stats = (const float*)d_in[3];
    const float* corr  = (const float*)d_in[4];
    const float* tW1  = (const float*)d_in[5];
    const float* tb1  = (const float*)d_in[6];
    const float* tg   = (const float*)d_in[7];
    const float* tbe  = (const float*)d_in[8];
    const float* tW2  = (const float*)d_in[9];
    const float* tb2  = (const float*)d_in[10];
    const float* sW1  = (const float*)d_in[11];
    const float* sb1  = (const float*)d_in[12];
    const float* sg   = (const float*)d_in[13];
    const float* sbe  = (const float*)d_in[14];
    const float* sW2  = (const float*)d_in[15];
    const float* sb2  = (const float*)d_in[16];
    const float* cW   = (const float*)d_in[17];
    const float* cb   = (const float*)d_in[18];

    static cudaStream_t s1 = nullptr, s2 = nullptr;
    static cudaEvent_t ev0, ev1, ev2, ev3, ev4, evU, evT;
    static int s_init = 0;
    if(!s_init){
        cudaFuncSetAttribute(k_gemm_t, cudaFuncAttributeMaxDynamicSharedMemorySize, SMEM_SZ);
        cudaFuncSetAttribute(k_gemm_s, cudaFuncAttributeMaxDynamicSharedMemorySize, SMEM_SZ);
        cudaFuncSetAttribute(k_gemm_u, cudaFuncAttributeMaxDynamicSharedMemorySize, SMEM_SZ);
        cudaFuncSetAttribute(k_corr_bf, cudaFuncAttributeMaxDynamicSharedMemorySize, SMEM_SZ);
        cudaStreamCreateWithFlags(&s1, cudaStreamNonBlocking);
        cudaStreamCreateWithFlags(&s2, cudaStreamNonBlocking);
        cudaEventCreateWithFlags(&ev0, cudaEventDisableTiming);
        cudaEventCreateWithFlags(&ev1, cudaEventDisableTiming);
        cudaEventCreateWithFlags(&ev2, cudaEventDisableTiming);
        cudaEventCreateWithFlags(&ev3, cudaEventDisableTiming);
        cudaEventCreateWithFlags(&ev4, cudaEventDisableTiming);
        cudaEventCreateWithFlags(&evU, cudaEventDisableTiming);
        cudaEventCreateWithFlags(&evT, cudaEventDisableTiming);
        s_init = 1;
    }

    dim3 tg3(16,16,3), tb_(32,8);
    dim3 gq(4, BNv/128);

    // fork point
    cudaEventRecord(ev0, 0);

    // main: e -> bf16
    k_cvt<<<(BNv*(Dv/4))/256,256>>>(e);

    // s1: weight transpose
    cudaStreamWaitEvent(s1, ev0, 0);
    k_transpose3<<<tg3,tb_,0,s1>>>(tW1, sW1, cW);
    cudaEventRecord(ev1, s1);

    // s2: mask detect + expand/count
    cudaStreamWaitEvent(s2, ev0, 0);
    k_detect<<<1,256,0,s2>>>((const unsigned int*)mraw);
    k_maskcnt<<<Bv,128,0,s2>>>(mraw);
    cudaEventRecord(ev2, s2);

    // main: U GEMM first
    cudaStreamWaitEvent(0, ev1, 0);
    k_gemm_u<<<gq,128,SMEM_SZ>>>();
    cudaEventRecord(evU, 0);

    // s1: corr — overlaps gemm_t + gemm_s on main
    cudaStreamWaitEvent(s1, evU, 0);
    cudaStreamWaitEvent(s1, ev2, 0);
    k_corr_bf<<<Bv,128,SMEM_SZ,s1>>>(corr, cb);
    cudaEventRecord(ev3, s1);

    // main: type GEMM
    k_gemm_t<<<gq,128,SMEM_SZ>>>(tb1);
    cudaEventRecord(evT, 0);

    // s2: type head — overlaps gemm_s
    cudaStreamWaitEvent(s2, evT, 0);
    k_type<<<BNv/8,256,0,s2>>>(tW2, tb2, tg, tbe, tgt);
    cudaEventRecord(ev4, s2);

    // main: stats GEMM then stats head
    k_gemm_s<<<gq,128,SMEM_SZ>>>(sb1);
    cudaStreamWaitEvent(0, ev2, 0);
    k_stats<<<BNv/8,256>>>(sW2, sb2, sg, sbe, stats);

    // main: final
    cudaStreamWaitEvent(0, ev3, 0);
    cudaStreamWaitEvent(0, ev4, 0);
    k_final<<<1,1024>>>((float*)d_out);
}

// round 17
// speedup vs baseline: 1.3300x; 1.3300x over previous
#include <cuda_runtime.h>
#include <cuda_bf16.h>
#include <math.h>
#include <stdint.h>

#define Bv 256
#define Nv 128
#define Dv 512
#define BNv (Bv*Nv)

// ---------------- device scratch ----------------
__device__ float         g_H [(size_t)BNv*Dv];
__device__ float         g_H2[(size_t)BNv*Dv];
__device__ __nv_bfloat16 g_Ebf[(size_t)BNv*Dv];
__device__ __nv_bfloat16 g_Ubf[(size_t)BNv*Dv];
__device__ __nv_bfloat16 g_WTbf[3*Dv*Dv];
__device__ float g_mask[BNv];
__device__ float g_cnt[Bv];
__device__ float g_part_t[BNv];
__device__ float g_part_s[BNv];
__device__ float g_part_c[Bv];
__device__ int   g_mfmt;

// ---------------- helpers ----------------
__device__ __forceinline__ uint32_t s2u(const void* p){
    uint32_t a;
    asm("{ .reg .u64 t; cvta.to.shared.u64 t, %1; cvt.u32.u64 %0, t; }":"=r"(a):"l"(p));
    return a;
}
__device__ __forceinline__ float htanh(float x){
    float t; asm("tanh.approx.f32 %0, %1;":"=f"(t):"f"(x));
    return t;
}
__device__ __forceinline__ float gelu_fast(float x){
    float x2 = x*x;
    float inner = x*fmaf(0.044715f*0.7978845608f, x2, 0.7978845608f);
    return 0.5f*x*(1.f + htanh(inner));
}
__device__ __forceinline__ void mma_bf16(float* d, const uint32_t* a, uint32_t b0, uint32_t b1){
    asm volatile(
      "mma.sync.aligned.m16n8k16.row.col.f32.bf16.bf16.f32 "
      "{%0,%1,%2,%3}, {%4,%5,%6,%7}, {%8,%9}, {%0,%1,%2,%3};"
      : "+f"(d[0]),"+f"(d[1]),"+f"(d[2]),"+f"(d[3])
      : "r"(a[0]),"r"(a[1]),"r"(a[2]),"r"(a[3]), "r"(b0),"r"(b1));
}
__device__ __forceinline__ void ldsm4(uint32_t addr, uint32_t* r){
    asm volatile("ldmatrix.sync.aligned.m8n8.x4.shared.b16 {%0,%1,%2,%3}, [%4];"
        : "=r"(r[0]),"=r"(r[1]),"=r"(r[2]),"=r"(r[3]) : "r"(addr));
}
__device__ __forceinline__ float warpAllSum(float v){
    #pragma unroll
    for(int o=16;o>0;o>>=1) v += __shfl_xor_sync(0xffffffffu, v, o);
    return v;
}
__device__ __forceinline__ uint32_t packbf(float a, float b){
    __nv_bfloat162 p = __floats2bfloat162_rn(a,b);
    return *reinterpret_cast<uint32_t*>(&p);
}

// ---------------- mask format detection + merged mask/count ----------------
__global__ void k_detect(const unsigned int* __restrict__ raw){
    __shared__ int f[2];
    if(threadIdx.x==0){ f[0]=1; f[1]=1; }
    __syncthreads();
    for(int i=threadIdx.x;i<8192;i+=256){
        unsigned v = raw[i];
        if(v>1u) f[0]=0;
        if(v!=0u && v!=0x3F800000u) f[1]=0;
    }
    __syncthreads();
    if(threadIdx.x==0) g_mfmt = f[0] ? 0 : (f[1] ? 1 : 2);
}
__global__ void k_maskcnt(const void* __restrict__ raw){
    int b = blockIdx.x, tid = threadIdx.x;
    int i = b*Nv + tid;
    int fmt = g_mfmt;
    float m;
    if(fmt==0)      m = (((const int*)raw)[i]   != 0)    ? 1.f : 0.f;
    else if(fmt==1) m = (((const float*)raw)[i] != 0.f)  ? 1.f : 0.f;
    else            m = (((const unsigned char*)raw)[i]!=0) ? 1.f : 0.f;
    g_mask[i] = m;
    float v = m;
    #pragma unroll
    for(int o=16;o>0;o>>=1) v += __shfl_down_sync(0xffffffffu, v, o);
    __shared__ float sh[4];
    if((tid&31)==0) sh[tid>>5] = v;
    __syncthreads();
    if(tid==0) g_cnt[b] = sh[0]+sh[1]+sh[2]+sh[3];
}

// ---------------- convert e -> bf16 ----------------
__global__ void k_cvt(const float* __restrict__ e){
    size_t i = (size_t)blockIdx.x*256 + threadIdx.x;
    float4 v = reinterpret_cast<const float4*>(e)[i];
    uint2 o;
    o.x = packbf(v.x, v.y);
    o.y = packbf(v.z, v.w);
    reinterpret_cast<uint2*>(g_Ebf)[i] = o;
}

// ---------------- weight transpose -> bf16 ----------------
__global__ void k_transpose3(const float* __restrict__ W0, const float* __restrict__ W1,
                             const float* __restrict__ W2){
    __shared__ float t[32][33];
    const float* W = (blockIdx.z==0) ? W0 : (blockIdx.z==1 ? W1 : W2);
    __nv_bfloat16* dst = g_WTbf + (size_t)blockIdx.z*Dv*Dv;
    int bx = blockIdx.x*32, by = blockIdx.y*32;
    int x = threadIdx.x, y = threadIdx.y;
    #pragma unroll
    for(int i=0;i<32;i+=8) t[y+i][x] = W[(size_t)(by+y+i)*Dv + bx+x];
    __syncthreads();
    #pragma unroll
    for(int i=0;i<32;i+=8) dst[(size_t)(bx+y+i)*Dv + by+x] = __float2bfloat16(t[x][y+i]);
}

// ---------------- bf16 mma GEMM core (R12: 256 threads, 32x64 warp tiles) ----------------
#define NCHB   8
#define STH    72
#define TILE_H (128*STH)
#define BUFB   36864
#define SMEM_SZ (2*BUFB)

// OUT 1 = GELU->g_H ; 2 = GELU->g_H2 ; 3 = U->g_Ubf ; 4 = corr epilogue
template<int OUT>
__device__ __forceinline__ void gemm_body(
    const __nv_bfloat16* __restrict__ Ab, const __nv_bfloat16* __restrict__ Bb,
    float* sm, uint32_t sb, int m0, int n0,
    const float* __restrict__ bias,
    const float* __restrict__ corr_t, const float* __restrict__ cb_ptr, int b){

    int tid = threadIdx.x, lane = tid&31, wid = tid>>5;
    int g = lane>>2, t = lane&3;
    int wm = (wid&3)*32, wn = (wid>>2)*64;

    int lrow = lane&15, lhi = lane>>4;
    uint32_t aoff[2], boff[4];
    #pragma unroll
    for(int mi=0;mi<2;mi++)
        aoff[mi] = (uint32_t)(((wm+mi*16+lrow)*36 + lhi*4)*4);
    #pragma unroll
    for(int p=0;p<4;p++)
        boff[p]  = (uint32_t)(TILE_H*2 + ((wn+p*16+lrow)*36 + lhi*4)*4);

    float acc[2][8][4];
    #pragma unroll
    for(int mi=0;mi<2;mi++)
        #pragma unroll
        for(int nj=0;nj<8;nj++)
            #pragma unroll
            for(int q=0;q<4;q++) acc[mi][nj][q]=0.f;

    auto stage = [&](int c, int buf){
        #pragma unroll
        for(int i=0;i<4;i++){
            int fi = tid + i*256;
            int row = fi>>3, q = fi&7;
            const __nv_bfloat16* ga = Ab + (size_t)row*Dv + c*64 + q*8;
            const __nv_bfloat16* gb = Bb + (size_t)row*Dv + c*64 + q*8;
            uint32_t da = sb + (uint32_t)(buf*BUFB + row*144 + q*16);
            uint32_t db = da + (uint32_t)(TILE_H*2);
            asm volatile("cp.async.ca.shared.global [%0], [%1], 16;"::"r"(da),"l"(ga):"memory");
            asm volatile("cp.async.ca.shared.global [%0], [%1], 16;"::"r"(db),"l"(gb):"memory");
        }
        asm volatile("cp.async.commit_group;":::"memory");
    };

    stage(0,0);

    #pragma unroll 1
    for(int c=0;c<NCHB;c++){
        if(c+1<NCHB){
            stage(c+1,(c+1)&1);
            asm volatile("cp.async.wait_group 1;":::"memory");
        }else{
            asm volatile("cp.async.wait_group 0;":::"memory");
        }
        __syncthreads();
        uint32_t base = sb + (uint32_t)((c&1)*BUFB);
        #pragma unroll
        for(int ki=0;ki<4;ki++){
            uint32_t af[2][4], bf[4][4];
            ldsm4(base + aoff[0] + ki*32, af[0]);
            ldsm4(base + aoff[1] + ki*32, af[1]);
            #pragma unroll
            for(int p=0;p<4;p++) ldsm4(base + boff[p] + ki*32, bf[p]);
            #pragma unroll
            for(int p=0;p<4;p++){
                mma_bf16(acc[0][2*p],   af[0], bf[p][0], bf[p][2]);
                mma_bf16(acc[1][2*p],   af[1], bf[p][0], bf[p][2]);
                mma_bf16(acc[0][2*p+1], af[0], bf[p][1], bf[p][3]);
                mma_bf16(acc[1][2*p+1], af[1], bf[p][1], bf[p][3]);
            }
        }
        __syncthreads();
    }

    if(OUT==1 || OUT==2){
        float* Hout = (OUT==1) ? g_H : g_H2;
        #pragma unroll
        for(int mi=0;mi<2;mi++){
            int r0 = m0 + wm + mi*16 + g;
            #pragma unroll
            for(int nj=0;nj<8;nj++){
                int cc = n0 + wn + nj*8 + 2*t;
                float bb0 = bias[cc], bb1 = bias[cc+1];
                float x0=gelu_fast(acc[mi][nj][0]+bb0), x1=gelu_fast(acc[mi][nj][1]+bb1);
                float x2=gelu_fast(acc[mi][nj][2]+bb0), x3=gelu_fast(acc[mi][nj][3]+bb1);
                *reinterpret_cast<float2*>(&Hout[(size_t)r0*Dv + cc])     = make_float2(x0,x1);
                *reinterpret_cast<float2*>(&Hout[(size_t)(r0+8)*Dv + cc]) = make_float2(x2,x3);
            }
        }
    }else if(OUT==3){
        #pragma unroll
        for(int mi=0;mi<2;mi++){
            int r0 = m0 + wm + mi*16 + g;
            #pragma unroll
            for(int nj=0;nj<8;nj++){
                int cc = n0 + wn + nj*8 + 2*t;
                *reinterpret_cast<uint32_t*>(&g_Ubf[(size_t)r0*Dv + cc])
                    = packbf(acc[mi][nj][0], acc[mi][nj][1]);
                *reinterpret_cast<uint32_t*>(&g_Ubf[(size_t)(r0+8)*Dv + cc])
                    = packbf(acc[mi][nj][2], acc[mi][nj][3]);
            }
        }
    }else{
        float cb = *cb_ptr;
        const float* msk = g_mask + b*Nv;
        const float* ct  = corr_t + (size_t)b*Nv*Nv;
        float local = 0.f;
        #pragma unroll
        for(int mi=0;mi<2;mi++){
            int r0 = wm + mi*16 + g;
            float mr0 = msk[r0], mr8 = msk[r0+8];
            #pragma unroll
            for(int nj=0;nj<8;nj++){
                int cc = wn + nj*8 + 2*t;
                float mc0 = msk[cc], mc1 = msk[cc+1];
                float2 t0 = *reinterpret_cast<const float2*>(&ct[(size_t)r0*Nv + cc]);
                float2 t1 = *reinterpret_cast<const float2*>(&ct[(size_t)(r0+8)*Nv + cc]);
                float s0 = (r0==cc)     ? 1.f : htanh(acc[mi][nj][0]+cb);
                float s1 = (r0==cc+1)   ? 1.f : htanh(acc[mi][nj][1]+cb);
                float s2 = (r0+8==cc)   ? 1.f : htanh(acc[mi][nj][2]+cb);
                float s3 = (r0+8==cc+1) ? 1.f : htanh(acc[mi][nj][3]+cb);
                float d0=s0-t0.x, d1=s1-t0.y, d2=s2-t1.x, d3=s3-t1.y;
                local += fmaxf(mr0,mc0)*d0*d0 + fmaxf(mr0,mc1)*d1*d1
                       + fmaxf(mr8,mc0)*d2*d2 + fmaxf(mr8,mc1)*d3*d3;
            }
        }
        #pragma unroll
        for(int o=16;o>0;o>>=1) local += __shfl_down_sync(0xffffffffu, local, o);
        if(lane==0) sm[wid] = local;
        __syncthreads();
        if(tid==0){
            float tot = 0.f;
            #pragma unroll
            for(int w=0;w<8;w++) tot += sm[w];
            g_part_c[b] = tot;
        }
    }
}

// head GEMMs: grid (8, 256); slot = bx>>2 in {0,1}
__global__ void __launch_bounds__(256,2)
k_gemm01(const float* __restrict__ tb1, const float* __restrict__ sb1){
    extern __shared__ float sm[];
    uint32_t sb = s2u(sm);
    int slot = blockIdx.x>>2;
    int n0 = (blockIdx.x&3)*128, m0 = blockIdx.y*128;
    const __nv_bfloat16* Ab = g_Ebf + (size_t)m0*Dv;
    const __nv_bfloat16* Bb = g_WTbf + (size_t)slot*Dv*Dv + (size_t)n0*Dv;
    if(slot==0) gemm_body<1>(Ab, Bb, sm, sb, m0, n0, tb1, nullptr, nullptr, 0);
    else        gemm_body<2>(Ab, Bb, sm, sb, m0, n0, sb1, nullptr, nullptr, 0);
}

// U GEMM: grid (4, 256)
__global__ void __launch_bounds__(256,2)
k_gemm_u(){
    extern __shared__ float sm[];
    uint32_t sb = s2u(sm);
    int n0 = blockIdx.x*128, m0 = blockIdx.y*128;
    const __nv_bfloat16* Ab = g_Ebf + (size_t)m0*Dv;
    const __nv_bfloat16* Bb = g_WTbf + (size_t)2*Dv*Dv + (size_t)n0*Dv;
    gemm_body<3>(Ab, Bb, sm, sb, m0, n0, nullptr, nullptr, nullptr, 0);
}

__global__ void __launch_bounds__(256,2)
k_corr_bf(const float* __restrict__ corr_t, const float* __restrict__ cb_ptr){
    extern __shared__ float sm[];
    uint32_t sb = s2u(sm);
    int b = blockIdx.x;
    const __nv_bfloat16* Ab = g_Ubf + (size_t)b*Nv*Dv;
    const __nv_bfloat16* Bb = g_Ebf + (size_t)b*Nv*Dv;
    gemm_body<4>(Ab, Bb, sm, sb, 0, 0, nullptr, corr_t, cb_ptr, b);
}

// ---------------- warp-per-row heads with shared W2/gamma/beta ----------------
__global__ void __launch_bounds__(256) k_type(const float* __restrict__ W2,
                                              const float* __restrict__ b2,
                                              const float* __restrict__ gam,
                                              const float* __restrict__ bet,
                                              const int* __restrict__ tgt){
    __shared__ float w2s[Dv*7];       // stride 7: conflict-free for lane stride 6*1? see analysis
    __shared__ float gs[Dv], bs[Dv];
    int tid = threadIdx.x;
    for(int i=tid;i<Dv;i+=256){
        #pragma unroll
        for(int c=0;c<6;c++) w2s[i*7+c] = W2[i*6+c];
        gs[i] = gam[i];
        bs[i] = bet[i];
    }
    __syncthreads();
    int wid = tid>>5, lane = tid&31;
    int row = blockIdx.x*8 + wid;
    const float* h = g_H + (size_t)row*Dv;
    float x[16];
    #pragma unroll
    for(int i=0;i<16;i++) x[i] = h[lane + 32*i];
    float s = 0.f;
    #pragma unroll
    for(int i=0;i<16;i++) s += x[i];
    float mu = warpAllSum(s) * (1.f/Dv);
    float vv = 0.f;
    #pragma unroll
    for(int i=0;i<16;i++){ float d=x[i]-mu; vv += d*d; }
    float rs = rsqrtf(warpAllSum(vv)*(1.f/Dv) + 1e-5f);
    float p[6] = {0,0,0,0,0,0};
    #pragma unroll
    for(int i=0;i<16;i++){
        int j = lane + 32*i;
        float y = (x[i]-mu)*rs*gs[j] + bs[j];
        #pragma unroll
        for(int c=0;c<6;c++) p[c] = fmaf(y, w2s[j*7+c], p[c]);
    }
    #pragma unroll
    for(int c=0;c<6;c++) p[c] = warpAllSum(p[c]);
    if(lane==0){
        float mx = -1e30f;
        #pragma unroll
        for(int c=0;c<6;c++){ p[c] += b2[c]; mx = fmaxf(mx, p[c]); }
        float se = 0.f;
        #pragma unroll
        for(int c=0;c<6;c++) se += expf(p[c]-mx);
        float lse = mx + logf(se);
        int tt = tgt[row & (Nv-1)];
        g_part_t[row] = g_mask[row] * (lse - p[tt]);
    }
}

__global__ void __launch_bounds__(256) k_stats(const float* __restrict__ W2,
                                               const float* __restrict__ b2,
                                               const float* __restrict__ gam,
                                               const float* __restrict__ bet,
                                               const float* __restrict__ st){
    __shared__ float w2s[Dv*9];       // stride 9: gcd(9,32)=1 -> conflict-free
    __shared__ float gs[Dv], bs[Dv];
    int tid = threadIdx.x;
    for(int i=tid;i<Dv;i+=256){
        #pragma unroll
        for(int c=0;c<8;c++) w2s[i*9+c] = W2[i*8+c];
        gs[i] = gam[i];
        bs[i] = bet[i];
    }
    __syncthreads();
    int wid = tid>>5, lane = tid&31;
    int row = blockIdx.x*8 + wid;
    const float* h = g_H2 + (size_t)row*Dv;
    float x[16];
    #pragma unroll
    for(int i=0;i<16;i++) x[i] = h[lane + 32*i];
    float s = 0.f;
    #pragma unroll
    for(int i=0;i<16;i++) s += x[i];
    float mu = warpAllSum(s) * (1.f/Dv);
    float vv = 0.f;
    #pragma unroll
    for(int i=0;i<16;i++){ float d=x[i]-mu; vv += d*d; }
    float rs = rsqrtf(warpAllSum(vv)*(1.f/Dv) + 1e-5f);
    float p[8] = {0,0,0,0,0,0,0,0};
    #pragma unroll
    for(int i=0;i<16;i++){
        int j = lane + 32*i;
        float y = (x[i]-mu)*rs*gs[j] + bs[j];
        #pragma unroll
        for(int c=0;c<8;c++) p[c] = fmaf(y, w2s[j*9+c], p[c]);
    }
    #pragma unroll
    for(int c=0;c<8;c++) p[c] = warpAllSum(p[c]);
    if(lane==0){
        float ssum = 0.f;
        #pragma unroll
        for(int c=0;c<8;c++){
            float d = p[c] + b2[c] - st[(size_t)row*8 + c];
            ssum += d*d;
        }
        g_part_s[row] = g_mask[row] * ssum;
    }
}

// ---------------- final deterministic combine ----------------
__global__ void k_final(float* __restrict__ out){
    __shared__ double sh[1024];
    int tid = threadIdx.x;
    double tsum=0, ssum=0, csum=0, nm=0, nme=0;
    for(int i=tid;i<BNv;i+=1024){ tsum += (double)g_part_t[i]; ssum += (double)g_part_s[i]; }
    for(int i=tid;i<Bv;i+=1024){
        csum += (double)g_part_c[i];
        double cnt = (double)g_cnt[i];
        nm += cnt;
        double u = (double)Nv - cnt;
        nme += (double)Nv*(double)Nv - u*u;
    }
    double vals[5] = {tsum, ssum, csum, nm, nme};
    for(int v=0;v<5;v++){
        sh[tid] = vals[v]; __syncthreads();
        for(int o=512;o>0;o>>=1){ if(tid<o) sh[tid]+=sh[tid+o]; __syncthreads(); }
        vals[v] = sh[0]; __syncthreads();
    }
    if(tid==0){
        double nm_  = vals[3] < 1.0 ? 1.0 : vals[3];
        double nme_ = vals[4] < 1.0 ? 1.0 : vals[4];
        double total = vals[0]/nm_ + vals[1]/(nm_*8.0) + 0.5*vals[2]/nme_;
        out[0] = (float)total;
    }
}

// ---------------- launch (R12 forked-stream graph) ----------------
extern "C" void kernel_launch(void* const* d_in, const int* in_sizes, int n_in,
                              void* d_out, int out_size){
    const float* e     = (const float*)d_in[0];
    const void*  mraw  = d_in[1];
    const int*   tgt   = (const int*)d_in[2];
    const float* stats = (const float*)d_in[3];
    const float* corr  = (const float*)d_in[4];
    const float* tW1  = (const float*)d_in[5];
    const float* tb1  = (const float*)d_in[6];
    const float* tg   = (const float*)d_in[7];
    const float* tbe  = (const float*)d_in[8];
    const float* tW2  = (const float*)d_in[9];
    const float* tb2  = (const float*)d_in[10];
    const float* sW1  = (const float*)d_in[11];
    const float* sb1  = (const float*)d_in[12];
    const float* sg   = (const float*)d_in[13];
    const float* sbe  = (const float*)d_in[14];
    const float* sW2  = (const float*)d_in[15];
    const float* sb2  = (const float*)d_in[16];
    const float* cW   = (const float*)d_in[17];
    const float* cb   = (const float*)d_in[18];

    static cudaStream_t s1 = nullptr, s2 = nullptr;
    static cudaEvent_t ev0, ev1, ev2, ev3, evA;
    static int s_init = 0;
    if(!s_init){
        cudaFuncSetAttribute(k_gemm01, cudaFuncAttributeMaxDynamicSharedMemorySize, SMEM_SZ);
        cudaFuncSetAttribute(k_gemm_u, cudaFuncAttributeMaxDynamicSharedMemorySize, SMEM_SZ);
        cudaFuncSetAttribute(k_corr_bf, cudaFuncAttributeMaxDynamicSharedMemorySize, SMEM_SZ);
        cudaStreamCreateWithFlags(&s1, cudaStreamNonBlocking);
        cudaStreamCreateWithFlags(&s2, cudaStreamNonBlocking);
        cudaEventCreateWithFlags(&ev0, cudaEventDisableTiming);
        cudaEventCreateWithFlags(&ev1, cudaEventDisableTiming);
        cudaEventCreateWithFlags(&ev2, cudaEventDisableTiming);
        cudaEventCreateWithFlags(&ev3, cudaEventDisableTiming);
        cudaEventCreateWithFlags(&evA, cudaEventDisableTiming);
        s_init = 1;
    }

    dim3 tg3(16,16,3), tb_(32,8);

    // fork point
    cudaEventRecord(ev0, 0);

    // main: e -> bf16
    k_cvt<<<(BNv*(Dv/4))/256,256>>>(e);

    // s1: weight transpose
    cudaStreamWaitEvent(s1, ev0, 0);
    k_transpose3<<<tg3,tb_,0,s1>>>(tW1, sW1, cW);
    cudaEventRecord(ev1, s1);

    // s2: mask detect + expand/count
    cudaStreamWaitEvent(s2, ev0, 0);
    k_detect<<<1,256,0,s2>>>((const unsigned int*)mraw);
    k_maskcnt<<<Bv,128,0,s2>>>(mraw);
    cudaEventRecord(ev2, s2);

    // main: head GEMMs (slots 0,1)
    cudaStreamWaitEvent(0, ev1, 0);
    dim3 gg01(8, BNv/128);
    k_gemm01<<<gg01,256,SMEM_SZ>>>(tb1, sb1);
    cudaEventRecord(evA, 0);

    // s1: U GEMM then corr — concurrent with heads on main
    cudaStreamWaitEvent(s1, evA, 0);
    dim3 ggu(4, BNv/128);
    k_gemm_u<<<ggu,256,SMEM_SZ,s1>>>();
    cudaStreamWaitEvent(s1, ev2, 0);
    k_corr_bf<<<Bv,256,SMEM_SZ,s1>>>(corr, cb);
    cudaEventRecord(ev3, s1);

    // main: heads (need gemm01 + mask)
    cudaStreamWaitEvent(0, ev2, 0);
    k_type <<<BNv/8,256>>>(tW2, tb2, tg, tbe, tgt);
    k_stats<<<BNv/8,256>>>(sW2, sb2, sg, sbe, stats);

    // main: final (needs corr branch too)
    cudaStreamWaitEvent(0, ev3, 0);
    k_final<<<1,1024>>>((float*)d_out);
}